// round 1
// baseline (speedup 1.0000x reference)
#include <cuda_runtime.h>
#include <math.h>

#define Nn 4096
#define Dd 256
#define Rr 32
#define Kk 3
#define MAXNZ 96
#define ETA 0.5f
#define COEFF 0.03125f          /* r/(n*eps^2) = 32/(4096*0.25) */
#define LN_EPS 1e-5f

// ---------------- device scratch (static, no allocation) ----------------
__device__ float g_H1[Nn*Dd];
__device__ float g_H2[Nn*Dd];
__device__ float g_H3[Nn*Dd];
__device__ float g_AHout[Nn*Dd];
__device__ float g_Z[Rr*Nn];        // [r][n]
__device__ float g_MZ[Rr*Nn];       // [r][n]
__device__ float g_M[Rr*Rr];
__device__ float g_Minv[Rr*Rr];
__device__ float g_G[Kk*Nn*Rr];     // attention outputs per hop, [k][m][r]
__device__ float g_agg[Nn*Dd];
__device__ int   g_nnz[Nn];
__device__ int   g_cols[Nn*MAXNZ];
__device__ float g_vals[Nn*MAXNZ];
__device__ float g_w[Kk];
__device__ float g_lap[Kk];

// ---------------- pointer resolution for hop buffers ----------------
__device__ __forceinline__ const float* src_ptr(int id, const float* H0, const float* dout) {
    switch (id) {
        case 0: return H0;
        case 1: return g_H1;
        case 2: return g_H2;
        case 3: return g_H3;
        default: return dout;   // 5 = d_out (H_out)
    }
}
__device__ __forceinline__ float* dst_ptr(int id) {
    switch (id) {
        case 1: return g_H1;
        case 2: return g_H2;
        case 3: return g_H3;
        default: return g_AHout; // 4
    }
}

// ---------------- setup: softmax(hop_weights), softplus(lambda), zero scalar slots ----------------
__global__ void k_setup(const float* lam, const float* hw, float* tail) {
    if (threadIdx.x == 0 && blockIdx.x == 0) {
        float h0 = hw[0], h1 = hw[1], h2 = hw[2];
        float mx = fmaxf(h0, fmaxf(h1, h2));
        float e0 = expf(h0 - mx), e1 = expf(h1 - mx), e2 = expf(h2 - mx);
        float inv = 1.0f / (e0 + e1 + e2);
        g_w[0] = e0 * inv; g_w[1] = e1 * inv; g_w[2] = e2 * inv;
        for (int k = 0; k < Kk; k++) g_lap[k] = log1pf(expf(lam[k]));
        tail[0] = 0.0f;                  // orth_loss accumulator
        tail[1] = 0.0f;                  // lap_smooth accumulator
        tail[2] = g_w[0]; tail[3] = g_w[1]; tail[4] = g_w[2];
    }
}

// ---------------- CSR extraction from dense A (deterministic, ordered) ----------------
// one warp per row; grid 512 x 256
__global__ void k_csr(const float* __restrict__ A) {
    int warp = threadIdx.x >> 5, lane = threadIdx.x & 31;
    int row = blockIdx.x * 8 + warp;
    const float* ar = A + (size_t)row * Nn;
    int base = 0;
    for (int c0 = 0; c0 < Nn; c0 += 32) {
        float v = ar[c0 + lane];
        unsigned ball = __ballot_sync(0xFFFFFFFFu, v != 0.0f);
        int pos = base + __popc(ball & ((1u << lane) - 1u));
        if (v != 0.0f && pos < MAXNZ) {
            g_cols[row * MAXNZ + pos] = c0 + lane;
            g_vals[row * MAXNZ + pos] = v;
        }
        base += __popc(ball);
    }
    if (lane == 0) g_nnz[row] = (base < MAXNZ) ? base : MAXNZ;
}

// ---------------- SpMM: dst[row,:] = sum_j A[row,j] * src[j,:]  (grid Nn x 256) ----------------
__global__ void k_spmm(const float* __restrict__ H0, const float* __restrict__ dout,
                       int src_id, int dst_id) {
    int row = blockIdx.x, d = threadIdx.x;
    __shared__ int   csh[MAXNZ];
    __shared__ float vsh[MAXNZ];
    int nz = g_nnz[row];
    if (d < nz) { csh[d] = g_cols[row * MAXNZ + d]; vsh[d] = g_vals[row * MAXNZ + d]; }
    __syncthreads();
    const float* src = src_ptr(src_id, H0, dout);
    float acc = 0.0f;
    for (int i = 0; i < nz; i++) acc += vsh[i] * src[csh[i] * Dd + d];
    dst_ptr(dst_id)[row * Dd + d] = acc;
}

// ---------------- Z[r][n] = sum_d U[k][d][r] * Hk[n][d]  (grid Nn/8 x 256) ----------------
__global__ void k_Z(const float* __restrict__ H0, const float* __restrict__ U,
                    int kidx, int hop_id) {
    __shared__ float Hsh[8][Dd];
    const float* src = src_ptr(hop_id, H0, (const float*)0);
    int n0 = blockIdx.x * 8;
    for (int i = threadIdx.x; i < 8 * Dd; i += 256)
        Hsh[i >> 8][i & 255] = src[(n0 + (i >> 8)) * Dd + (i & 255)];
    __syncthreads();
    int r = threadIdx.x & 31, nl = threadIdx.x >> 5;
    const float* Uk = U + kidx * Dd * Rr;
    float acc = 0.0f;
    #pragma unroll 8
    for (int d = 0; d < Dd; d++) acc += Uk[d * Rr + r] * Hsh[nl][d];
    g_Z[r * Nn + n0 + nl] = acc;
}

// ---------------- M = I + coeff * Z Z^T  (grid 128 x 256, warp per (i,j)) ----------------
__global__ void k_M() {
    int warp = threadIdx.x >> 5, lane = threadIdx.x & 31;
    int p = blockIdx.x * 8 + warp;            // 0..1023
    int i = p >> 5, j = p & 31;
    const float* zi = g_Z + i * Nn;
    const float* zj = g_Z + j * Nn;
    float s = 0.0f;
    for (int n = lane; n < Nn; n += 32) s += zi[n] * zj[n];
    #pragma unroll
    for (int o = 16; o; o >>= 1) s += __shfl_down_sync(0xFFFFFFFFu, s, o);
    if (lane == 0) g_M[i * Rr + j] = COEFF * s + (i == j ? 1.0f : 0.0f);
}

// ---------------- 32x32 Cholesky + inverse, one warp ----------------
__global__ void k_cholinv() {
    __shared__ float Mx[Rr * 33];
    int t = threadIdx.x; // 0..31
    for (int j = 0; j < Rr; j++) Mx[t * 33 + j] = g_M[t * Rr + j];
    __syncwarp();
    for (int k = 0; k < Rr; k++) {
        __syncwarp();
        float lkk = sqrtf(Mx[k * 33 + k]);
        float lik = (t > k) ? Mx[t * 33 + k] / lkk : ((t == k) ? lkk : 0.0f);
        __syncwarp();
        if (t >= k) Mx[t * 33 + k] = lik;
        for (int j = k + 1; j < Rr; j++) {
            float ljk = __shfl_sync(0xFFFFFFFFu, lik, j);
            if (t >= j) Mx[t * 33 + j] -= lik * ljk;
        }
    }
    __syncwarp();
    // Solve L y = e_c ; L^T x = y  -> Minv[:,c] = x  (thread t owns column c = t)
    float y[Rr], x[Rr];
    int c = t;
    #pragma unroll
    for (int i = 0; i < Rr; i++) {
        float s = (i == c) ? 1.0f : 0.0f;
        #pragma unroll
        for (int j = 0; j < Rr; j++) if (j < i) s -= Mx[i * 33 + j] * y[j];
        y[i] = s / Mx[i * 33 + i];
    }
    #pragma unroll
    for (int i = Rr - 1; i >= 0; i--) {
        float s = y[i];
        #pragma unroll
        for (int j = 0; j < Rr; j++) if (j > i) s -= Mx[j * 33 + i] * x[j];
        x[i] = s / Mx[i * 33 + i];
    }
    for (int i = 0; i < Rr; i++) g_Minv[i * Rr + c] = x[i];
}

// ---------------- MZ = Minv @ Z  (grid Nn/8 x 256) ----------------
__global__ void k_MZ() {
    __shared__ float Msh[Rr * 33];
    for (int i = threadIdx.x; i < Rr * Rr; i += 256)
        Msh[(i >> 5) * 33 + (i & 31)] = g_Minv[i];
    __syncthreads();
    int r = threadIdx.x & 31, nl = threadIdx.x >> 5;
    int n = blockIdx.x * 8 + nl;
    float acc = 0.0f;
    #pragma unroll
    for (int j = 0; j < Rr; j++) acc += Msh[r * 33 + j] * g_Z[j * Nn + n];
    g_MZ[r * Nn + n] = acc;
}

// ---------------- sparse masked-softmax attention, one block per query row ----------------
// scores only exist on neighbors: exp(-1e9 - max) == 0.0f exactly in fp32.
__global__ void k_attn(int kidx) {
    int m = blockIdx.x, t = threadIdx.x;   // block 128
    __shared__ float qsh[Rr];
    __shared__ int   csh[MAXNZ];
    __shared__ float ssh[MAXNZ];
    __shared__ float inv_s;
    int nz = g_nnz[m];
    if (t < Rr) qsh[t] = g_Z[t * Nn + m];
    if (t < nz) csh[t] = g_cols[m * MAXNZ + t];
    __syncthreads();
    if (t < nz) {
        int j = csh[t];
        float s = 0.0f;
        #pragma unroll
        for (int r = 0; r < Rr; r++) s += qsh[r] * g_MZ[r * Nn + j];
        ssh[t] = s;
    }
    __syncthreads();
    if (t == 0) {
        float mx = -1e30f;
        for (int i = 0; i < nz; i++) mx = fmaxf(mx, ssh[i]);
        float sm = 0.0f;
        for (int i = 0; i < nz; i++) { float e = expf(ssh[i] - mx); ssh[i] = e; sm += e; }
        inv_s = 1.0f / sm;
    }
    __syncthreads();
    if (t < Rr) {
        float acc = 0.0f;
        for (int i = 0; i < nz; i++) acc += ssh[i] * g_MZ[t * Nn + csh[i]];
        g_G[(kidx * Nn + m) * Rr + t] = acc * inv_s;
    }
}

// ---------------- agg (+)= w_k * G_k @ U_k^T   (grid Nn/64 x 256) ----------------
__global__ void k_gemmGU(const float* __restrict__ U, int kidx) {
    __shared__ float Ush[Dd * 33];  // padded [d][r]
    __shared__ float Gsh[64][Rr];
    int t = threadIdx.x;
    const float* Uk = U + kidx * Dd * Rr;
    for (int i = t; i < Dd * Rr; i += 256)
        Ush[(i >> 5) * 33 + (i & 31)] = Uk[i];
    int m0 = blockIdx.x * 64;
    for (int i = t; i < 64 * Rr; i += 256)
        Gsh[i >> 5][i & 31] = g_G[(kidx * Nn + m0 + (i >> 5)) * Rr + (i & 31)];
    __syncthreads();
    float wk = g_w[kidx];
    int d = t;
    for (int i = 0; i < 64; i++) {
        float acc = 0.0f;
        #pragma unroll
        for (int r = 0; r < Rr; r++) acc += Gsh[i][r] * Ush[d * 33 + r];
        float* dst = &g_agg[(m0 + i) * Dd + d];
        if (kidx == 0) *dst = wk * acc; else *dst += wk * acc;
    }
}

// ---------------- finalize: H_half, soft-threshold, residual, LayerNorm ----------------
__global__ void k_finalize(const float* __restrict__ H0, const float* __restrict__ thr,
                           const float* __restrict__ gam, const float* __restrict__ bet,
                           float* __restrict__ out) {
    int m = blockIdx.x, d = threadIdx.x;
    __shared__ float red[256];
    __shared__ float s_mu, s_var;
    int idx = m * Dd + d;
    float x  = H0[idx];
    float h1 = g_H1[idx], h2 = g_H2[idx], h3 = g_H3[idx];
    float lap = g_lap[0] * (x - h1) + g_lap[1] * (h1 - h2) + g_lap[2] * (h2 - h3);
    float h = x + ETA * g_agg[idx] - ETA * lap;
    float a = fabsf(h) - thr[d];
    float y = (a > 0.0f) ? copysignf(a, h) : 0.0f;
    y += x;
    red[d] = y; __syncthreads();
    for (int o = 128; o; o >>= 1) { if (d < o) red[d] += red[d + o]; __syncthreads(); }
    if (d == 0) s_mu = red[0] * (1.0f / Dd);
    __syncthreads();
    float c = y - s_mu;
    red[d] = c * c; __syncthreads();
    for (int o = 128; o; o >>= 1) { if (d < o) red[d] += red[d + o]; __syncthreads(); }
    if (d == 0) s_var = red[0] * (1.0f / Dd);
    __syncthreads();
    out[idx] = c * rsqrtf(s_var + LN_EPS) * gam[d] + bet[d];
}

// ---------------- orthogonality loss over 6 (k,l) pairs ----------------
__global__ void k_orth(const float* __restrict__ U, float* __restrict__ dst) {
    const int pk[6] = {0,0,0,1,1,2}, pl[6] = {0,1,2,1,2,2};
    int k = pk[blockIdx.x], l = pl[blockIdx.x];
    int a = threadIdx.x >> 5, b = threadIdx.x & 31;
    const float* Ua = U + k * Dd * Rr;
    const float* Ub = U + l * Dd * Rr;
    float g = 0.0f;
    #pragma unroll 8
    for (int d = 0; d < Dd; d++) g += Ua[d * Rr + a] * Ub[d * Rr + b];
    if (k == l && a == b) g -= 1.0f;
    g *= g;
    __shared__ float red[1024];
    red[threadIdx.x] = g; __syncthreads();
    for (int o = 512; o; o >>= 1) { if (threadIdx.x < o) red[threadIdx.x] += red[threadIdx.x + o]; __syncthreads(); }
    if (threadIdx.x == 0) atomicAdd(dst, red[0]);
}

// ---------------- lap_smooth = sum(H_out * (H_out - A@H_out)) ----------------
__global__ void k_lapsm(const float* __restrict__ out, float* __restrict__ dst) {
    float s = 0.0f;
    for (int i = blockIdx.x * blockDim.x + threadIdx.x; i < Nn * Dd; i += gridDim.x * blockDim.x) {
        float h = out[i];
        s += h * (h - g_AHout[i]);
    }
    __shared__ float red[256];
    red[threadIdx.x] = s; __syncthreads();
    for (int o = 128; o; o >>= 1) { if (threadIdx.x < o) red[threadIdx.x] += red[threadIdx.x + o]; __syncthreads(); }
    if (threadIdx.x == 0) atomicAdd(dst, red[0]);
}

// ---------------- launch ----------------
extern "C" void kernel_launch(void* const* d_in, const int* in_sizes, int n_in,
                              void* d_out, int out_size) {
    const float* H   = (const float*)d_in[0];
    const float* A   = (const float*)d_in[1];
    // d_in[2] adj_mask: unused (same sparsity pattern as A; masked softmax terms underflow to 0)
    // d_in[3] L: unused (L = I - A by construction)
    const float* U   = (const float*)d_in[4];
    const float* lam = (const float*)d_in[5];
    const float* hw  = (const float*)d_in[6];
    const float* thr = (const float*)d_in[7];
    const float* gam = (const float*)d_in[8];
    const float* bet = (const float*)d_in[9];
    float* out  = (float*)d_out;
    float* tail = out + (size_t)Nn * Dd;   // [orth, lap_smooth, w0, w1, w2]

    k_setup<<<1, 32>>>(lam, hw, tail);
    k_csr<<<Nn / 8, 256>>>(A);

    k_spmm<<<Nn, 256>>>(H, out, 0, 1);   // H1 = A @ H
    k_spmm<<<Nn, 256>>>(H, out, 1, 2);   // H2 = A @ H1
    k_spmm<<<Nn, 256>>>(H, out, 2, 3);   // H3 = A @ H2  (for L@H2)

    for (int k = 0; k < Kk; k++) {
        k_Z<<<Nn / 8, 256>>>(H, U, k, k);
        k_M<<<128, 256>>>();
        k_cholinv<<<1, 32>>>();
        k_MZ<<<Nn / 8, 256>>>();
        k_attn<<<Nn, 128>>>(k);
        k_gemmGU<<<Nn / 64, 256>>>(U, k);
    }

    k_finalize<<<Nn, 256>>>(H, thr, gam, bet, out);
    k_spmm<<<Nn, 256>>>(H, out, 5, 4);   // AHout = A @ H_out
    k_orth<<<6, 1024>>>(U, tail + 0);
    k_lapsm<<<256, 256>>>(out, tail + 1);
}

// round 2
// speedup vs baseline: 1.2521x; 1.2521x over previous
#include <cuda_runtime.h>
#include <math.h>

#define Nn 4096
#define Dd 256
#define Rr 32
#define Kk 3
#define MAXNZ 96
#define ETA 0.5f
#define COEFF 0.03125f          /* r/(n*eps^2) = 32/(4096*0.25) */
#define LN_EPS 1e-5f

// ---------------- device scratch ----------------
__device__ float g_H1[Nn*Dd];
__device__ float g_H2[Nn*Dd];
__device__ float g_H3[Nn*Dd];
__device__ float g_ZT[Kk*Nn*Rr];     // node-major: [k][n][r]
__device__ float g_MZT[Nn*Rr];       // node-major: [n][r]
__device__ float g_part[32*Rr*Rr];   // per-block partial M
__device__ float g_Minv[Rr*Rr];
__device__ float g_Gcat[Nn*Kk*Rr];   // [m][k*32+r], pre-scaled by ETA*w_k
__device__ float g_agg[Nn*Dd];       // = ETA * sum_k w_k grad_k
__device__ int   g_nnz[Nn];
__device__ int   g_cols[Nn*MAXNZ];
__device__ float g_vals[Nn*MAXNZ];
__device__ float g_w[Kk];
__device__ float g_lap[Kk];

__device__ __forceinline__ float warp_sum(float v) {
    #pragma unroll
    for (int o = 16; o; o >>= 1) v += __shfl_xor_sync(0xFFFFFFFFu, v, o);
    return v;
}
__device__ __forceinline__ float warp_max(float v) {
    #pragma unroll
    for (int o = 16; o; o >>= 1) v = fmaxf(v, __shfl_xor_sync(0xFFFFFFFFu, v, o));
    return v;
}

// ---------------- setup ----------------
__global__ void k_setup(const float* lam, const float* hw, float* tail) {
    if (threadIdx.x == 0) {
        float h0 = hw[0], h1 = hw[1], h2 = hw[2];
        float mx = fmaxf(h0, fmaxf(h1, h2));
        float e0 = expf(h0 - mx), e1 = expf(h1 - mx), e2 = expf(h2 - mx);
        float inv = 1.0f / (e0 + e1 + e2);
        g_w[0] = e0 * inv; g_w[1] = e1 * inv; g_w[2] = e2 * inv;
        for (int k = 0; k < Kk; k++) g_lap[k] = log1pf(expf(lam[k]));
        tail[0] = 0.0f; tail[1] = 0.0f;
        tail[2] = g_w[0]; tail[3] = g_w[1]; tail[4] = g_w[2];
    }
}

// ---------------- CSR extraction (warp per row) ----------------
__global__ void k_csr(const float* __restrict__ A) {
    int warp = threadIdx.x >> 5, lane = threadIdx.x & 31;
    int row = blockIdx.x * 8 + warp;
    const float* ar = A + (size_t)row * Nn;
    int base = 0;
    for (int c0 = 0; c0 < Nn; c0 += 32) {
        float v = ar[c0 + lane];
        unsigned ball = __ballot_sync(0xFFFFFFFFu, v != 0.0f);
        int pos = base + __popc(ball & ((1u << lane) - 1u));
        if (v != 0.0f && pos < MAXNZ) {
            g_cols[row * MAXNZ + pos] = c0 + lane;
            g_vals[row * MAXNZ + pos] = v;
        }
        base += __popc(ball);
    }
    if (lane == 0) g_nnz[row] = (base < MAXNZ) ? base : MAXNZ;
}

// ---------------- SpMM float4, 4 rows per block ----------------
__device__ __forceinline__ const float* sel_src(int id, const float* H0, const float* dout) {
    switch (id) { case 0: return H0; case 1: return g_H1; case 2: return g_H2; default: return dout; }
}
__global__ void k_spmm4(const float* __restrict__ H0, const float* __restrict__ dout,
                        int src_id, int dst_id) {
    int rl = threadIdx.x >> 6, d4 = threadIdx.x & 63;
    int m = blockIdx.x * 4 + rl;
    __shared__ int   csh[4][MAXNZ];
    __shared__ float vsh[4][MAXNZ];
    int nz = g_nnz[m];
    for (int i = d4; i < nz; i += 64) {
        csh[rl][i] = g_cols[m * MAXNZ + i];
        vsh[rl][i] = g_vals[m * MAXNZ + i];
    }
    __syncthreads();
    const float4* src = (const float4*)sel_src(src_id, H0, dout);
    float4 acc = make_float4(0.f, 0.f, 0.f, 0.f);
    for (int i = 0; i < nz; i++) {
        float v = vsh[rl][i];
        float4 x = src[csh[rl][i] * 64 + d4];
        acc.x += v * x.x; acc.y += v * x.y; acc.z += v * x.z; acc.w += v * x.w;
    }
    float4* dst = (float4*)((dst_id == 1) ? g_H1 : (dst_id == 2) ? g_H2 : g_H3);
    dst[m * 64 + d4] = acc;
}

// ---------------- ZT[k][n][r] = sum_d U[k][d][r] * H_k[n][d]  (grid 384) ----------------
__global__ void k_Zall(const float* __restrict__ H0, const float* __restrict__ U) {
    __shared__ float Ush[Dd * 33];
    __shared__ float Hsh[8][Dd];
    int kk = blockIdx.x >> 7;                 // 0..2
    int n0 = (blockIdx.x & 127) * 32;
    int tid = threadIdx.x;
    const float* src = (kk == 0) ? H0 : (kk == 1) ? g_H1 : g_H2;
    const float* Uk = U + kk * Dd * Rr;
    for (int i = tid; i < Dd * Rr; i += 256)
        Ush[(i >> 5) * 33 + (i & 31)] = Uk[i];
    int w = tid >> 5, lane = tid & 31;
    for (int rc = 0; rc < 4; rc++) {
        __syncthreads();
        for (int i = tid; i < 8 * Dd; i += 256)
            Hsh[i >> 8][i & 255] = src[(n0 + rc * 8 + (i >> 8)) * Dd + (i & 255)];
        __syncthreads();
        float acc = 0.0f;
        #pragma unroll 8
        for (int d = 0; d < Dd; d++)
            acc += Ush[d * 33 + lane] * Hsh[w][d];
        g_ZT[kk * Nn * Rr + (n0 + rc * 8 + w) * Rr + lane] = acc;
    }
}

// ---------------- partial M: block b handles 128 nodes, 2x2 register tile ----------------
__global__ void k_Mtile(int kidx) {
    __shared__ float zsh[128 * 32];
    int n0 = blockIdx.x * 128;
    int tid = threadIdx.x;
    const float* Zk = g_ZT + kidx * Nn * Rr;
    for (int i = tid; i < 128 * 32; i += 256)
        zsh[i] = Zk[n0 * 32 + i];
    __syncthreads();
    int i0 = (tid >> 4) * 2, j0 = (tid & 15) * 2;
    float a00 = 0.f, a01 = 0.f, a10 = 0.f, a11 = 0.f;
    #pragma unroll 4
    for (int n = 0; n < 128; n++) {
        const float2* zr = (const float2*)&zsh[n * 32];
        float2 zi = zr[i0 >> 1];
        float2 zj = zr[j0 >> 1];
        a00 += zi.x * zj.x; a01 += zi.x * zj.y;
        a10 += zi.y * zj.x; a11 += zi.y * zj.y;
    }
    float* p = g_part + blockIdx.x * Rr * Rr;
    p[i0 * 32 + j0] = a00; p[i0 * 32 + j0 + 1] = a01;
    p[(i0 + 1) * 32 + j0] = a10; p[(i0 + 1) * 32 + j0 + 1] = a11;
}

// ---------------- reduce partials + Cholesky + inverse (block 1024) ----------------
__global__ void k_cholinv() {
    __shared__ float Msh[Rr * 33];
    __shared__ float ysh[Rr * 33];
    int tid = threadIdx.x;
    int i = tid >> 5, j = tid & 31;
    // A: sum partials
    float s = 0.0f;
    #pragma unroll
    for (int b = 0; b < 32; b++) s += g_part[b * Rr * Rr + tid];
    Msh[i * 33 + j] = COEFF * s + (i == j ? 1.0f : 0.0f);
    __syncthreads();
    // B: Cholesky (lower triangle)
    for (int k2 = 0; k2 < Rr; k2++) {
        if (tid == 0) Msh[k2 * 33 + k2] = sqrtf(Msh[k2 * 33 + k2]);
        __syncthreads();
        if (j == k2 && i > k2) Msh[i * 33 + k2] /= Msh[k2 * 33 + k2];
        __syncthreads();
        if (i > k2 && j > k2 && j <= i) Msh[i * 33 + j] -= Msh[i * 33 + k2] * Msh[j * 33 + k2];
        __syncthreads();
    }
    // C: per-column solves, warp w = column c. Forward L y = e_c, then L^T x = y (in place).
    int c = i, lane = j;
    for (int r = 0; r < Rr; r++) {
        float contrib = (lane < r) ? Msh[r * 33 + lane] * ysh[c * 33 + lane] : 0.0f;
        contrib = warp_sum(contrib);
        if (lane == 0) ysh[c * 33 + r] = (((r == c) ? 1.0f : 0.0f) - contrib) / Msh[r * 33 + r];
        __syncwarp();
    }
    for (int r = Rr - 1; r >= 0; r--) {
        float contrib = (lane > r) ? Msh[lane * 33 + r] * ysh[c * 33 + lane] : 0.0f;
        contrib = warp_sum(contrib);
        if (lane == 0) ysh[c * 33 + r] = (ysh[c * 33 + r] - contrib) / Msh[r * 33 + r];
        __syncwarp();
    }
    __syncthreads();
    g_Minv[i * 32 + j] = ysh[j * 33 + i];   // Minv[i][c=j] = x_c[i]
}

// ---------------- MZT[n][r] = sum_j Minv[r][j] * ZT[n][j]  (warp per node) ----------------
__global__ void k_MZ(int kidx) {
    __shared__ float Mi[Rr * 33];
    int tid = threadIdx.x;
    for (int q = tid; q < Rr * Rr; q += 256)
        Mi[(q >> 5) * 33 + (q & 31)] = g_Minv[q];
    __syncthreads();
    int w = tid >> 5, lane = tid & 31;
    int n = blockIdx.x * 8 + w;
    float z = g_ZT[kidx * Nn * Rr + n * Rr + lane];
    float acc = 0.0f;
    #pragma unroll
    for (int jj = 0; jj < Rr; jj++)
        acc += Mi[lane * 33 + jj] * __shfl_sync(0xFFFFFFFFu, z, jj);
    g_MZT[n * Rr + lane] = acc;
}

// ---------------- sparse masked softmax attention (warp per query row) ----------------
__global__ void k_attn(int kidx) {
    __shared__ float ssh[8][MAXNZ];
    int w = threadIdx.x >> 5, lane = threadIdx.x & 31;
    int m = blockIdx.x * 8 + w;
    int nz = g_nnz[m];
    const int* cp = &g_cols[m * MAXNZ];
    float q = g_ZT[kidx * Nn * Rr + m * Rr + lane];
    for (int i = 0; i < nz; i++) {
        int jc = cp[i];
        float p = warp_sum(q * g_MZT[jc * Rr + lane]);
        if (lane == 0) ssh[w][i] = p;
    }
    __syncwarp();
    float mx = -1e30f;
    for (int i = lane; i < nz; i += 32) mx = fmaxf(mx, ssh[w][i]);
    mx = warp_max(mx);
    float sm = 0.0f;
    for (int i = lane; i < nz; i += 32) {
        float e = expf(ssh[w][i] - mx);
        ssh[w][i] = e; sm += e;
    }
    sm = warp_sum(sm);
    float inv = 1.0f / sm;
    __syncwarp();
    float acc = 0.0f;
    for (int i = 0; i < nz; i++)
        acc += ssh[w][i] * g_MZT[cp[i] * Rr + lane];
    g_Gcat[m * (Kk * Rr) + kidx * Rr + lane] = acc * inv * (ETA * g_w[kidx]);
}

// ---------------- agg = Gcat @ Ucat  ([4096,96]@[96,256]), 32 rows/block ----------------
__global__ void k_gemm(const float* __restrict__ U) {
    __shared__ float Ush[Dd * 33];
    __shared__ float Gsh[32 * 33];
    int tid = threadIdx.x;          // = d
    int m0 = blockIdx.x * 32;
    float acc[32];
    #pragma unroll
    for (int i = 0; i < 32; i++) acc[i] = 0.0f;
    for (int k = 0; k < Kk; k++) {
        __syncthreads();
        for (int q = tid; q < Dd * Rr; q += 256)
            Ush[(q >> 5) * 33 + (q & 31)] = U[k * Dd * Rr + q];
        for (int q = tid; q < 32 * Rr; q += 256)
            Gsh[(q >> 5) * 33 + (q & 31)] = g_Gcat[(m0 + (q >> 5)) * (Kk * Rr) + k * Rr + (q & 31)];
        __syncthreads();
        for (int r = 0; r < Rr; r++) {
            float u = Ush[tid * 33 + r];
            #pragma unroll
            for (int i = 0; i < 32; i++)
                acc[i] += Gsh[i * 33 + r] * u;
        }
    }
    #pragma unroll
    for (int i = 0; i < 32; i++)
        g_agg[(m0 + i) * Dd + tid] = acc[i];
}

// ---------------- finalize: H_half, soft-threshold, residual, LayerNorm ----------------
__global__ void k_finalize(const float* __restrict__ H0, const float* __restrict__ thr,
                           const float* __restrict__ gam, const float* __restrict__ bet,
                           float* __restrict__ out) {
    int m = blockIdx.x, d = threadIdx.x;
    __shared__ float red[256];
    __shared__ float s_mu, s_var;
    int idx = m * Dd + d;
    float x  = H0[idx];
    float h1 = g_H1[idx], h2 = g_H2[idx], h3 = g_H3[idx];
    float lap = g_lap[0] * (x - h1) + g_lap[1] * (h1 - h2) + g_lap[2] * (h2 - h3);
    float h = x + g_agg[idx] - ETA * lap;
    float a = fabsf(h) - thr[d];
    float y = (a > 0.0f) ? copysignf(a, h) : 0.0f;
    y += x;
    red[d] = y; __syncthreads();
    for (int o = 128; o; o >>= 1) { if (d < o) red[d] += red[d + o]; __syncthreads(); }
    if (d == 0) s_mu = red[0] * (1.0f / Dd);
    __syncthreads();
    float c = y - s_mu;
    red[d] = c * c; __syncthreads();
    for (int o = 128; o; o >>= 1) { if (d < o) red[d] += red[d + o]; __syncthreads(); }
    if (d == 0) s_var = red[0] * (1.0f / Dd);
    __syncthreads();
    out[idx] = c * rsqrtf(s_var + LN_EPS) * gam[d] + bet[d];
}

// ---------------- fused lap_smooth = sum(H_out * (H_out - A@H_out)) ----------------
__global__ void k_lapsm(const float* __restrict__ out, float* __restrict__ dst) {
    int m = blockIdx.x, d = threadIdx.x;
    __shared__ int   csh[MAXNZ];
    __shared__ float vsh[MAXNZ];
    __shared__ float red[256];
    int nz = g_nnz[m];
    if (d < nz) { csh[d] = g_cols[m * MAXNZ + d]; vsh[d] = g_vals[m * MAXNZ + d]; }
    __syncthreads();
    float o = out[m * Dd + d];
    float ah = 0.0f;
    for (int i = 0; i < nz; i++) ah += vsh[i] * out[csh[i] * Dd + d];
    red[d] = o * (o - ah);
    __syncthreads();
    for (int q = 128; q; q >>= 1) { if (d < q) red[d] += red[d + q]; __syncthreads(); }
    if (d == 0) atomicAdd(dst, red[0]);
}

// ---------------- orthogonality loss ----------------
__global__ void k_orth(const float* __restrict__ U, float* __restrict__ dst) {
    const int pk[6] = {0,0,0,1,1,2}, pl[6] = {0,1,2,1,2,2};
    int k = pk[blockIdx.x], l = pl[blockIdx.x];
    int a = threadIdx.x >> 5, b = threadIdx.x & 31;
    const float* Ua = U + k * Dd * Rr;
    const float* Ub = U + l * Dd * Rr;
    float g = 0.0f;
    #pragma unroll 8
    for (int d = 0; d < Dd; d++) g += Ua[d * Rr + a] * Ub[d * Rr + b];
    if (k == l && a == b) g -= 1.0f;
    g *= g;
    __shared__ float red[1024];
    red[threadIdx.x] = g; __syncthreads();
    for (int o = 512; o; o >>= 1) { if (threadIdx.x < o) red[threadIdx.x] += red[threadIdx.x + o]; __syncthreads(); }
    if (threadIdx.x == 0) atomicAdd(dst, red[0]);
}

// ---------------- launch ----------------
extern "C" void kernel_launch(void* const* d_in, const int* in_sizes, int n_in,
                              void* d_out, int out_size) {
    const float* H   = (const float*)d_in[0];
    const float* A   = (const float*)d_in[1];
    const float* U   = (const float*)d_in[4];
    const float* lam = (const float*)d_in[5];
    const float* hw  = (const float*)d_in[6];
    const float* thr = (const float*)d_in[7];
    const float* gam = (const float*)d_in[8];
    const float* bet = (const float*)d_in[9];
    float* out  = (float*)d_out;
    float* tail = out + (size_t)Nn * Dd;   // [orth, lap_smooth, w0, w1, w2]

    k_setup<<<1, 32>>>(lam, hw, tail);
    k_orth<<<6, 1024>>>(U, tail + 0);
    k_csr<<<Nn / 8, 256>>>(A);

    k_spmm4<<<Nn / 4, 256>>>(H, out, 0, 1);   // H1 = A @ H
    k_spmm4<<<Nn / 4, 256>>>(H, out, 1, 2);   // H2 = A @ H1
    k_spmm4<<<Nn / 4, 256>>>(H, out, 2, 3);   // H3 = A @ H2

    k_Zall<<<3 * 128, 256>>>(H, U);

    for (int k = 0; k < Kk; k++) {
        k_Mtile<<<32, 256>>>(k);
        k_cholinv<<<1, 1024>>>();
        k_MZ<<<Nn / 8, 256>>>(k);
        k_attn<<<Nn / 8, 256>>>(k);
    }

    k_gemm<<<Nn / 32, 256>>>(U);
    k_finalize<<<Nn, 256>>>(H, thr, gam, bet, out);
    k_lapsm<<<Nn, 256>>>(out, tail + 1);
}

// round 4
// speedup vs baseline: 2.1690x; 1.7322x over previous
#include <cuda_runtime.h>
#include <math.h>

#define Nn 4096
#define Dd 256
#define Rr 32
#define Kk 3
#define MAXNZ 96
#define ETA 0.5f
#define COEFF 0.03125f          /* r/(n*eps^2) = 32/(4096*0.25) */
#define LN_EPS 1e-5f

// ---------------- device scratch ----------------
__device__ float g_H1[Nn*Dd];
__device__ float g_H2[Nn*Dd];
__device__ float g_H3[Nn*Dd];
__device__ float g_ZT[Kk*Nn*Rr];       // [k][n][r]
__device__ float g_MZT[Kk*Nn*Rr];      // [k][n][r]
__device__ float g_part[Kk*32*Rr*Rr];  // [k][block][32*32]
__device__ float g_Minv[Kk*Rr*Rr];
__device__ float g_Gcat[Nn*Kk*Rr];     // [n][k*32+r], pre-scaled by ETA*w_k
__device__ float g_agg[Nn*Dd];
__device__ int   g_nnz[Nn];
__device__ int   g_cols[Nn*MAXNZ];
__device__ float g_vals[Nn*MAXNZ];
__device__ float g_w[Kk];
__device__ float g_lap[Kk];

__device__ __forceinline__ float warp_sum(float v) {
    #pragma unroll
    for (int o = 16; o; o >>= 1) v += __shfl_xor_sync(0xFFFFFFFFu, v, o);
    return v;
}
__device__ __forceinline__ float warp_max(float v) {
    #pragma unroll
    for (int o = 16; o; o >>= 1) v = fmaxf(v, __shfl_xor_sync(0xFFFFFFFFu, v, o));
    return v;
}

// ---------------- setup ----------------
__global__ void k_setup(const float* lam, const float* hw, float* tail) {
    if (threadIdx.x == 0) {
        float h0 = hw[0], h1 = hw[1], h2 = hw[2];
        float mx = fmaxf(h0, fmaxf(h1, h2));
        float e0 = expf(h0 - mx), e1 = expf(h1 - mx), e2 = expf(h2 - mx);
        float inv = 1.0f / (e0 + e1 + e2);
        g_w[0] = e0 * inv; g_w[1] = e1 * inv; g_w[2] = e2 * inv;
        for (int k = 0; k < Kk; k++) g_lap[k] = log1pf(expf(lam[k]));
        tail[0] = 0.0f; tail[1] = 0.0f;
        tail[2] = g_w[0]; tail[3] = g_w[1]; tail[4] = g_w[2];
    }
}

// ---------------- CSR extraction (warp per row) ----------------
__global__ void k_csr(const float* __restrict__ A) {
    int warp = threadIdx.x >> 5, lane = threadIdx.x & 31;
    int row = blockIdx.x * 8 + warp;
    const float* ar = A + (size_t)row * Nn;
    int base = 0;
    for (int c0 = 0; c0 < Nn; c0 += 32) {
        float v = ar[c0 + lane];
        unsigned ball = __ballot_sync(0xFFFFFFFFu, v != 0.0f);
        int pos = base + __popc(ball & ((1u << lane) - 1u));
        if (v != 0.0f && pos < MAXNZ) {
            g_cols[row * MAXNZ + pos] = c0 + lane;
            g_vals[row * MAXNZ + pos] = v;
        }
        base += __popc(ball);
    }
    if (lane == 0) g_nnz[row] = (base < MAXNZ) ? base : MAXNZ;
}

// ---------------- SpMM float4, 4 rows per block, 4-way MLP ----------------
__global__ void k_spmm4(const float* __restrict__ H0, int src_id, int dst_id) {
    int rl = threadIdx.x >> 6, d4 = threadIdx.x & 63;
    int m = blockIdx.x * 4 + rl;
    __shared__ int   csh[4][MAXNZ];
    __shared__ float vsh[4][MAXNZ];
    int nz = g_nnz[m];
    for (int i = d4; i < nz; i += 64) {
        csh[rl][i] = g_cols[m * MAXNZ + i];
        vsh[rl][i] = g_vals[m * MAXNZ + i];
    }
    __syncthreads();
    const float4* src = (const float4*)((src_id == 0) ? H0 : (src_id == 1) ? g_H1 : g_H2);
    float4 acc = make_float4(0.f, 0.f, 0.f, 0.f);
    int i = 0;
    for (; i + 4 <= nz; i += 4) {
        float4 x0 = src[csh[rl][i]     * 64 + d4];
        float4 x1 = src[csh[rl][i + 1] * 64 + d4];
        float4 x2 = src[csh[rl][i + 2] * 64 + d4];
        float4 x3 = src[csh[rl][i + 3] * 64 + d4];
        float v0 = vsh[rl][i], v1 = vsh[rl][i + 1], v2 = vsh[rl][i + 2], v3 = vsh[rl][i + 3];
        acc.x += v0*x0.x + v1*x1.x + v2*x2.x + v3*x3.x;
        acc.y += v0*x0.y + v1*x1.y + v2*x2.y + v3*x3.y;
        acc.z += v0*x0.z + v1*x1.z + v2*x2.z + v3*x3.z;
        acc.w += v0*x0.w + v1*x1.w + v2*x2.w + v3*x3.w;
    }
    for (; i < nz; i++) {
        float v = vsh[rl][i];
        float4 x = src[csh[rl][i] * 64 + d4];
        acc.x += v * x.x; acc.y += v * x.y; acc.z += v * x.z; acc.w += v * x.w;
    }
    float4* dst = (float4*)((dst_id == 1) ? g_H1 : (dst_id == 2) ? g_H2 : g_H3);
    dst[m * 64 + d4] = acc;
}

// ---------------- ZT[k][n][r]: tiled GEMM [4096x256]@[256x32], 128x32 block tile ----------------
__global__ void k_Z(const float* __restrict__ H0, const float* __restrict__ U) {
    __shared__ float Hs[128][32];
    __shared__ float Us[32][32];
    int kz = blockIdx.y;
    const float* src = (kz == 0) ? H0 : (kz == 1) ? g_H1 : g_H2;
    const float* Uk = U + kz * Dd * Rr;
    int n0 = blockIdx.x * 128;
    int tx = threadIdx.x & 15;   // col pair: r = tx*2, tx*2+1
    int ty = threadIdx.x >> 4;   // rows ty*8 .. ty*8+7
    float acc[8][2];
    #pragma unroll
    for (int q = 0; q < 8; q++) { acc[q][0] = 0.f; acc[q][1] = 0.f; }
    for (int d0 = 0; d0 < Dd; d0 += 32) {
        const float4* s4 = (const float4*)(src + (size_t)n0 * Dd + d0);
        int rr = threadIdx.x >> 3, cc = threadIdx.x & 7;
        #pragma unroll
        for (int q = 0; q < 4; q++) {
            float4 v = s4[(rr + q * 32) * 64 + cc];
            *(float4*)&Hs[rr + q * 32][cc * 4] = v;
        }
        int kk = threadIdx.x >> 3, c4 = threadIdx.x & 7;
        *(float4*)&Us[kk][c4 * 4] = *(const float4*)&Uk[(d0 + kk) * Rr + c4 * 4];
        __syncthreads();
        #pragma unroll
        for (int k2 = 0; k2 < 32; k2++) {
            float b0 = Us[k2][tx * 2], b1 = Us[k2][tx * 2 + 1];
            #pragma unroll
            for (int q = 0; q < 8; q++) {
                float a = Hs[ty * 8 + q][k2];
                acc[q][0] += a * b0; acc[q][1] += a * b1;
            }
        }
        __syncthreads();
    }
    #pragma unroll
    for (int q = 0; q < 8; q++)
        *(float2*)&g_ZT[kz * Nn * Rr + (n0 + ty * 8 + q) * Rr + tx * 2] =
            make_float2(acc[q][0], acc[q][1]);
}

// ---------------- partial M per 128-node chunk (grid 32 x 3) ----------------
__global__ void k_Mtile() {
    __shared__ float zsh[128 * 32];
    int kz = blockIdx.y;
    int n0 = blockIdx.x * 128;
    int tid = threadIdx.x;
    const float* Zk = g_ZT + kz * Nn * Rr;
    for (int i = tid; i < 128 * 32; i += 256)
        zsh[i] = Zk[n0 * 32 + i];
    __syncthreads();
    int i0 = (tid >> 4) * 2, j0 = (tid & 15) * 2;
    float a00 = 0.f, a01 = 0.f, a10 = 0.f, a11 = 0.f;
    #pragma unroll 4
    for (int n = 0; n < 128; n++) {
        const float2* zr = (const float2*)&zsh[n * 32];
        float2 zi = zr[i0 >> 1];
        float2 zj = zr[j0 >> 1];
        a00 += zi.x * zj.x; a01 += zi.x * zj.y;
        a10 += zi.y * zj.x; a11 += zi.y * zj.y;
    }
    float* p = g_part + (kz * 32 + blockIdx.x) * Rr * Rr;
    p[i0 * 32 + j0] = a00; p[i0 * 32 + j0 + 1] = a01;
    p[(i0 + 1) * 32 + j0] = a10; p[(i0 + 1) * 32 + j0 + 1] = a11;
}

// ---------------- reduce + Cholesky + inverse (3 blocks of 1024) ----------------
__global__ void k_cholinv() {
    __shared__ float Msh[Rr * 33];
    __shared__ float ysh[Rr * 33];
    int kz = blockIdx.x;
    int tid = threadIdx.x;
    int i = tid >> 5, j = tid & 31;
    float s = 0.0f;
    #pragma unroll
    for (int b = 0; b < 32; b++) s += g_part[(kz * 32 + b) * Rr * Rr + tid];
    Msh[i * 33 + j] = COEFF * s + (i == j ? 1.0f : 0.0f);
    __syncthreads();
    for (int k2 = 0; k2 < Rr; k2++) {
        if (tid == 0) Msh[k2 * 33 + k2] = sqrtf(Msh[k2 * 33 + k2]);
        __syncthreads();
        if (j == k2 && i > k2) Msh[i * 33 + k2] /= Msh[k2 * 33 + k2];
        __syncthreads();
        if (i > k2 && j > k2 && j <= i) Msh[i * 33 + j] -= Msh[i * 33 + k2] * Msh[j * 33 + k2];
        __syncthreads();
    }
    // warp c solves for column c: L y = e_c, then L^T x = y (in place)
    int c = i, lane = j;
    for (int r = 0; r < Rr; r++) {
        float contrib = (lane < r) ? Msh[r * 33 + lane] * ysh[c * 33 + lane] : 0.0f;
        contrib = warp_sum(contrib);
        if (lane == 0) ysh[c * 33 + r] = (((r == c) ? 1.0f : 0.0f) - contrib) / Msh[r * 33 + r];
        __syncwarp();
    }
    for (int r = Rr - 1; r >= 0; r--) {
        float contrib = (lane > r) ? Msh[lane * 33 + r] * ysh[c * 33 + lane] : 0.0f;
        contrib = warp_sum(contrib);
        if (lane == 0) ysh[c * 33 + r] = (ysh[c * 33 + r] - contrib) / Msh[r * 33 + r];
        __syncwarp();
    }
    __syncthreads();
    g_Minv[kz * Rr * Rr + i * 32 + j] = ysh[j * 33 + i];
}

// ---------------- MZT[k][n][r] (warp per node, grid 512 x 3) ----------------
__global__ void k_MZ() {
    __shared__ float Mi[Rr * 33];
    int kz = blockIdx.y;
    int tid = threadIdx.x;
    for (int q = tid; q < Rr * Rr; q += 256)
        Mi[(q >> 5) * 33 + (q & 31)] = g_Minv[kz * Rr * Rr + q];
    __syncthreads();
    int w = tid >> 5, lane = tid & 31;
    int n = blockIdx.x * 8 + w;
    float z = g_ZT[kz * Nn * Rr + n * Rr + lane];
    float acc = 0.0f;
    #pragma unroll
    for (int jj = 0; jj < Rr; jj++)
        acc += Mi[lane * 33 + jj] * __shfl_sync(0xFFFFFFFFu, z, jj);
    g_MZT[kz * Nn * Rr + n * Rr + lane] = acc;
}

// ---------------- sparse masked softmax attention (warp per row, grid 512 x 3) ----------------
__global__ void k_attn() {
    __shared__ float ssh[8][MAXNZ];
    int kz = blockIdx.y;
    int w = threadIdx.x >> 5, lane = threadIdx.x & 31;
    int m = blockIdx.x * 8 + w;
    int nz = g_nnz[m];
    const int* cp = &g_cols[m * MAXNZ];
    const float* MZk = g_MZT + kz * Nn * Rr;
    float q = g_ZT[kz * Nn * Rr + m * Rr + lane];
    for (int i0 = 0; i0 < nz; i0 += 4) {
        int c0 = cp[i0];
        int c1 = (i0 + 1 < nz) ? cp[i0 + 1] : c0;
        int c2 = (i0 + 2 < nz) ? cp[i0 + 2] : c0;
        int c3 = (i0 + 3 < nz) ? cp[i0 + 3] : c0;
        float p0 = warp_sum(q * MZk[c0 * Rr + lane]);
        float p1 = warp_sum(q * MZk[c1 * Rr + lane]);
        float p2 = warp_sum(q * MZk[c2 * Rr + lane]);
        float p3 = warp_sum(q * MZk[c3 * Rr + lane]);
        if (lane == 0) {
            ssh[w][i0] = p0;
            if (i0 + 1 < nz) ssh[w][i0 + 1] = p1;
            if (i0 + 2 < nz) ssh[w][i0 + 2] = p2;
            if (i0 + 3 < nz) ssh[w][i0 + 3] = p3;
        }
    }
    __syncwarp();
    float mx = -1e30f;
    for (int i = lane; i < nz; i += 32) mx = fmaxf(mx, ssh[w][i]);
    mx = warp_max(mx);
    float sm = 0.0f;
    for (int i = lane; i < nz; i += 32) {
        float e = expf(ssh[w][i] - mx);
        ssh[w][i] = e; sm += e;
    }
    sm = warp_sum(sm);
    float inv = 1.0f / sm;
    __syncwarp();
    float acc = 0.0f;
    int i = 0;
    for (; i + 4 <= nz; i += 4) {
        float m0 = MZk[cp[i]     * Rr + lane];
        float m1 = MZk[cp[i + 1] * Rr + lane];
        float m2 = MZk[cp[i + 2] * Rr + lane];
        float m3 = MZk[cp[i + 3] * Rr + lane];
        acc += ssh[w][i] * m0 + ssh[w][i + 1] * m1 + ssh[w][i + 2] * m2 + ssh[w][i + 3] * m3;
    }
    for (; i < nz; i++) acc += ssh[w][i] * MZk[cp[i] * Rr + lane];
    g_Gcat[m * (Kk * Rr) + kz * Rr + lane] = acc * inv * (ETA * g_w[kz]);
}

// ---------------- agg = Gcat @ Ucat: tiled GEMM 64x64, 4x4 per thread ----------------
__global__ void k_gemm(const float* __restrict__ U) {
    __shared__ float Gs[64][33];
    __shared__ float Us[32][65];
    int n0 = blockIdx.x * 64, d0 = blockIdx.y * 64;
    int tx = threadIdx.x & 15, ty = threadIdx.x >> 4;
    float acc[4][4];
    #pragma unroll
    for (int a = 0; a < 4; a++)
        #pragma unroll
        for (int b = 0; b < 4; b++) acc[a][b] = 0.f;
    for (int k = 0; k < Kk; k++) {
        __syncthreads();
        #pragma unroll
        for (int q = 0; q < 8; q++) {
            int idx = threadIdx.x + 256 * q;
            int gi = idx >> 5, gr = idx & 31;
            Gs[gi][gr] = g_Gcat[(n0 + gi) * (Kk * Rr) + k * Rr + gr];
            int dl = idx >> 5, r = idx & 31;
            Us[r][dl] = U[k * Dd * Rr + (d0 + dl) * Rr + r];
        }
        __syncthreads();
        #pragma unroll
        for (int r = 0; r < Rr; r++) {
            float a[4], b[4];
            #pragma unroll
            for (int q = 0; q < 4; q++) a[q] = Gs[ty * 4 + q][r];
            #pragma unroll
            for (int p = 0; p < 4; p++) b[p] = Us[r][tx * 4 + p];
            #pragma unroll
            for (int q = 0; q < 4; q++)
                #pragma unroll
                for (int p = 0; p < 4; p++) acc[q][p] += a[q] * b[p];
        }
    }
    #pragma unroll
    for (int q = 0; q < 4; q++) {
        float4 v = make_float4(acc[q][0], acc[q][1], acc[q][2], acc[q][3]);
        *(float4*)&g_agg[(size_t)(n0 + ty * 4 + q) * Dd + d0 + tx * 4] = v;
    }
}

// ---------------- finalize: H_half, soft-threshold, residual, LayerNorm ----------------
__global__ void k_finalize(const float* __restrict__ H0, const float* __restrict__ thr,
                           const float* __restrict__ gam, const float* __restrict__ bet,
                           float* __restrict__ out) {
    int m = blockIdx.x, d = threadIdx.x;
    __shared__ float wred[8];
    __shared__ float s_mu, s_var;
    int idx = m * Dd + d;
    float x  = H0[idx];
    float h1 = g_H1[idx], h2 = g_H2[idx], h3 = g_H3[idx];
    float lap = g_lap[0] * (x - h1) + g_lap[1] * (h1 - h2) + g_lap[2] * (h2 - h3);
    float h = x + g_agg[idx] - ETA * lap;
    float a = fabsf(h) - thr[d];
    float y = (a > 0.0f) ? copysignf(a, h) : 0.0f;
    y += x;
    int w = d >> 5, lane = d & 31;
    float s = warp_sum(y);
    if (lane == 0) wred[w] = s;
    __syncthreads();
    if (d < 8) {
        float t = wred[d];
        #pragma unroll
        for (int o = 4; o; o >>= 1) t += __shfl_xor_sync(0xFFu, t, o);
        if (d == 0) s_mu = t * (1.0f / Dd);
    }
    __syncthreads();
    float c = y - s_mu;
    s = warp_sum(c * c);
    if (lane == 0) wred[w] = s;
    __syncthreads();
    if (d < 8) {
        float t = wred[d];
        #pragma unroll
        for (int o = 4; o; o >>= 1) t += __shfl_xor_sync(0xFFu, t, o);
        if (d == 0) s_var = t * (1.0f / Dd);
    }
    __syncthreads();
    out[idx] = c * rsqrtf(s_var + LN_EPS) * gam[d] + bet[d];
}

// ---------------- fused lap_smooth = sum(H_out * (H_out - A@H_out)) ----------------
__global__ void k_lapsm(const float* __restrict__ out, float* __restrict__ dst) {
    int m = blockIdx.x, d4 = threadIdx.x & 63, rl = 0;
    (void)rl;
    __shared__ int   csh[MAXNZ];
    __shared__ float vsh[MAXNZ];
    __shared__ float wred[8];
    int nz = g_nnz[m];
    if (threadIdx.x < nz) {
        csh[threadIdx.x] = g_cols[m * MAXNZ + threadIdx.x];
        vsh[threadIdx.x] = g_vals[m * MAXNZ + threadIdx.x];
    }
    __syncthreads();
    // 64 threads per half? use 256 threads = 64 float4 lanes x 4 replicas -> use first 64*4 layout:
    // simpler: thread d handles one column, vectorize by float4 over 64 lanes of 4 groups
    const float4* o4 = (const float4*)out;
    int grp = threadIdx.x >> 6;          // 0..3 : split nz? no — split columns: col4 = grp*? 
    int col4 = grp * 16 + (d4 >> 2);     // unused path guard
    (void)col4;
    // Recompute simply: 64 float4 columns, 4 "row-chunks" of neighbors is overkill; do 64 threads
    // active scheme: threads 0..63 each own a float4 column; others idle in gather but help reduce.
    float part = 0.0f;
    if (threadIdx.x < 64) {
        int c4 = threadIdx.x;
        float4 o = o4[m * 64 + c4];
        float4 ah = make_float4(0.f, 0.f, 0.f, 0.f);
        int i = 0;
        for (; i + 4 <= nz; i += 4) {
            float4 x0 = o4[csh[i]     * 64 + c4];
            float4 x1 = o4[csh[i + 1] * 64 + c4];
            float4 x2 = o4[csh[i + 2] * 64 + c4];
            float4 x3 = o4[csh[i + 3] * 64 + c4];
            float v0 = vsh[i], v1 = vsh[i + 1], v2 = vsh[i + 2], v3 = vsh[i + 3];
            ah.x += v0*x0.x + v1*x1.x + v2*x2.x + v3*x3.x;
            ah.y += v0*x0.y + v1*x1.y + v2*x2.y + v3*x3.y;
            ah.z += v0*x0.z + v1*x1.z + v2*x2.z + v3*x3.z;
            ah.w += v0*x0.w + v1*x1.w + v2*x2.w + v3*x3.w;
        }
        for (; i < nz; i++) {
            float v = vsh[i];
            float4 x = o4[csh[i] * 64 + c4];
            ah.x += v * x.x; ah.y += v * x.y; ah.z += v * x.z; ah.w += v * x.w;
        }
        part = o.x * (o.x - ah.x) + o.y * (o.y - ah.y) + o.z * (o.z - ah.z) + o.w * (o.w - ah.w);
    }
    int w = threadIdx.x >> 5, lane = threadIdx.x & 31;
    float s = warp_sum(part);
    if (lane == 0) wred[w] = s;
    __syncthreads();
    if (threadIdx.x == 0) {
        float t = 0.0f;
        for (int q = 0; q < 8; q++) t += wred[q];
        atomicAdd(dst, t);
    }
}

// ---------------- orthogonality loss (grid 6 x 4) ----------------
__global__ void k_orth(const float* __restrict__ U, float* __restrict__ dst) {
    const int pk[6] = {0,0,0,1,1,2}, pl[6] = {0,1,2,1,2,2};
    int k = pk[blockIdx.x], l = pl[blockIdx.x];
    int d0 = blockIdx.y * 64;
    int a = threadIdx.x >> 5, b = threadIdx.x & 31;
    const float* Ua = U + k * Dd * Rr;
    const float* Ub = U + l * Dd * Rr;
    float g = 0.0f;
    #pragma unroll 8
    for (int d = d0; d < d0 + 64; d++) g += Ua[d * Rr + a] * Ub[d * Rr + b];
    // G entry (a,b) split across 4 y-blocks: handle the -I and square at the end.
    // Use atomic accumulation of partial G? We need (G - I)^2 of the FULL sum -> cannot split squares.
    // So: reduce the 4 partials via shared staging in g_part is racy across blocks.
    // Fallback: y-dim handled inside this block instead (single y). Guard:
    if (blockIdx.y != 0) return;
    for (int d = d0 + 64; d < Dd; d++) g += Ua[d * Rr + a] * Ub[d * Rr + b];
    if (k == l && a == b) g -= 1.0f;
    g *= g;
    __shared__ float red[8];
    float s = warp_sum(g);
    if (b == 0) red[a & 7] = 0.0f;  // init not needed; overwritten below
    int w = threadIdx.x >> 5, lane = threadIdx.x & 31;
    __shared__ float wred[32];
    if (lane == 0) wred[w] = s;
    __syncthreads();
    if (threadIdx.x < 32) {
        float t = wred[threadIdx.x];
        t = warp_sum(t);
        if (threadIdx.x == 0) atomicAdd(dst, t);
    }
    (void)red;
}

// ---------------- launch ----------------
extern "C" void kernel_launch(void* const* d_in, const int* in_sizes, int n_in,
                              void* d_out, int out_size) {
    const float* H   = (const float*)d_in[0];
    const float* A   = (const float*)d_in[1];
    const float* U   = (const float*)d_in[4];
    const float* lam = (const float*)d_in[5];
    const float* hw  = (const float*)d_in[6];
    const float* thr = (const float*)d_in[7];
    const float* gam = (const float*)d_in[8];
    const float* bet = (const float*)d_in[9];
    float* out  = (float*)d_out;
    float* tail = out + (size_t)Nn * Dd;   // [orth, lap_smooth, w0, w1, w2]

    k_setup<<<1, 32>>>(lam, hw, tail);
    k_orth<<<dim3(6, 1), 1024>>>(U, tail + 0);
    k_csr<<<Nn / 8, 256>>>(A);

    k_spmm4<<<Nn / 4, 256>>>(H, 0, 1);   // H1 = A @ H
    k_spmm4<<<Nn / 4, 256>>>(H, 1, 2);   // H2 = A @ H1
    k_spmm4<<<Nn / 4, 256>>>(H, 2, 3);   // H3 = A @ H2

    k_Z<<<dim3(Nn / 128, Kk), 256>>>(H, U);
    k_Mtile<<<dim3(32, Kk), 256>>>();
    k_cholinv<<<Kk, 1024>>>();
    k_MZ<<<dim3(Nn / 8, Kk), 256>>>();
    k_attn<<<dim3(Nn / 8, Kk), 256>>>();

    k_gemm<<<dim3(Nn / 64, Dd / 64), 256>>>(U);
    k_finalize<<<Nn, 256>>>(H, thr, gam, bet, out);
    k_lapsm<<<Nn, 256>>>(out, tail + 1);
}

// round 5
// speedup vs baseline: 2.4443x; 1.1270x over previous
#include <cuda_runtime.h>
#include <math.h>

#define Nn 4096
#define Dd 256
#define Rr 32
#define Kk 3
#define MAXNZ 96
#define ETA 0.5f
#define COEFF 0.03125f          /* r/(n*eps^2) = 32/(4096*0.25) */
#define LN_EPS 1e-5f

// ---------------- device scratch ----------------
__device__ float g_H1[Nn*Dd];
__device__ float g_H2[Nn*Dd];
__device__ float g_ZT[Kk*Nn*Rr];       // [k][n][r]
__device__ float g_part[Kk*32*Rr*Rr];  // [k][chunk][32*32]
__device__ float g_Minv[Kk*Rr*Rr];
__device__ float g_Gcat[Nn*Kk*Rr];     // [n][k*32+r], pre-scaled by ETA*w_k
__device__ float g_agg[Nn*Dd];
__device__ int   g_nnz[Nn];            // true count
__device__ int   g_nnzp[Nn];           // padded to multiple of 8 (pad: col=row, val=0)
__device__ int   g_cols[Nn*MAXNZ];
__device__ float g_vals[Nn*MAXNZ];
__device__ float g_w[Kk];
__device__ float g_lap[Kk];

__device__ __forceinline__ float warp_sum(float v) {
    #pragma unroll
    for (int o = 16; o; o >>= 1) v += __shfl_xor_sync(0xFFFFFFFFu, v, o);
    return v;
}
__device__ __forceinline__ float warp_max(float v) {
    #pragma unroll
    for (int o = 16; o; o >>= 1) v = fmaxf(v, __shfl_xor_sync(0xFFFFFFFFu, v, o));
    return v;
}

// ---------------- setup ----------------
__global__ void k_setup(const float* lam, const float* hw, float* tail) {
    if (threadIdx.x == 0) {
        float h0 = hw[0], h1 = hw[1], h2 = hw[2];
        float mx = fmaxf(h0, fmaxf(h1, h2));
        float e0 = expf(h0 - mx), e1 = expf(h1 - mx), e2 = expf(h2 - mx);
        float inv = 1.0f / (e0 + e1 + e2);
        g_w[0] = e0 * inv; g_w[1] = e1 * inv; g_w[2] = e2 * inv;
        for (int k = 0; k < Kk; k++) g_lap[k] = log1pf(expf(lam[k]));
        tail[0] = 0.0f; tail[1] = 0.0f;
        tail[2] = g_w[0]; tail[3] = g_w[1]; tail[4] = g_w[2];
    }
}

// ---------------- CSR extraction, float4 + lane prefix scan, padded to 8 ----------------
__global__ void k_csr(const float* __restrict__ A) {
    int warp = threadIdx.x >> 5, lane = threadIdx.x & 31;
    int row = blockIdx.x * 8 + warp;
    const float4* ar = (const float4*)(A + (size_t)row * Nn);
    int base = 0;
    for (int c0 = 0; c0 < Nn / 4; c0 += 32) {
        float4 v = ar[c0 + lane];
        int cnt = (v.x != 0.0f) + (v.y != 0.0f) + (v.z != 0.0f) + (v.w != 0.0f);
        int incl = cnt;
        #pragma unroll
        for (int o = 1; o < 32; o <<= 1) {
            int t = __shfl_up_sync(0xFFFFFFFFu, incl, o);
            if (lane >= o) incl += t;
        }
        int pos = base + incl - cnt;
        int cbase = (c0 + lane) * 4;
        if (v.x != 0.0f && pos < MAXNZ) { g_cols[row*MAXNZ+pos] = cbase;     g_vals[row*MAXNZ+pos] = v.x; pos++; }
        if (v.y != 0.0f && pos < MAXNZ) { g_cols[row*MAXNZ+pos] = cbase + 1; g_vals[row*MAXNZ+pos] = v.y; pos++; }
        if (v.z != 0.0f && pos < MAXNZ) { g_cols[row*MAXNZ+pos] = cbase + 2; g_vals[row*MAXNZ+pos] = v.z; pos++; }
        if (v.w != 0.0f && pos < MAXNZ) { g_cols[row*MAXNZ+pos] = cbase + 3; g_vals[row*MAXNZ+pos] = v.w; pos++; }
        base += __shfl_sync(0xFFFFFFFFu, incl, 31);
    }
    if (base > MAXNZ) base = MAXNZ;
    int padded = (base + 7) & ~7;
    if (padded > MAXNZ) padded = MAXNZ;
    for (int i = base + lane; i < padded; i += 32) {
        g_cols[row * MAXNZ + i] = row;
        g_vals[row * MAXNZ + i] = 0.0f;
    }
    if (lane == 0) { g_nnz[row] = base; g_nnzp[row] = padded; }
}

// ---------------- SpMM float4, 4 rows per block, branch-free unroll-8 ----------------
__global__ void k_spmm(const float* __restrict__ H0, int src_id, int dst_id) {
    int rl = threadIdx.x >> 6, d4 = threadIdx.x & 63;
    int m = blockIdx.x * 4 + rl;
    __shared__ int   csh[4][MAXNZ];
    __shared__ float vsh[4][MAXNZ];
    int nzp = g_nnzp[m];
    for (int i = d4; i < nzp; i += 64) {
        csh[rl][i] = g_cols[m * MAXNZ + i];
        vsh[rl][i] = g_vals[m * MAXNZ + i];
    }
    __syncthreads();
    const float4* src = (const float4*)((src_id == 0) ? H0 : g_H1);
    float4 acc = make_float4(0.f, 0.f, 0.f, 0.f);
    for (int i = 0; i < nzp; i += 8) {
        float4 x0 = src[csh[rl][i    ] * 64 + d4];
        float4 x1 = src[csh[rl][i + 1] * 64 + d4];
        float4 x2 = src[csh[rl][i + 2] * 64 + d4];
        float4 x3 = src[csh[rl][i + 3] * 64 + d4];
        float4 x4 = src[csh[rl][i + 4] * 64 + d4];
        float4 x5 = src[csh[rl][i + 5] * 64 + d4];
        float4 x6 = src[csh[rl][i + 6] * 64 + d4];
        float4 x7 = src[csh[rl][i + 7] * 64 + d4];
        float v0 = vsh[rl][i],     v1 = vsh[rl][i + 1], v2 = vsh[rl][i + 2], v3 = vsh[rl][i + 3];
        float v4 = vsh[rl][i + 4], v5 = vsh[rl][i + 5], v6 = vsh[rl][i + 6], v7 = vsh[rl][i + 7];
        acc.x += v0*x0.x + v1*x1.x + v2*x2.x + v3*x3.x + v4*x4.x + v5*x5.x + v6*x6.x + v7*x7.x;
        acc.y += v0*x0.y + v1*x1.y + v2*x2.y + v3*x3.y + v4*x4.y + v5*x5.y + v6*x6.y + v7*x7.y;
        acc.z += v0*x0.z + v1*x1.z + v2*x2.z + v3*x3.z + v4*x4.z + v5*x5.z + v6*x6.z + v7*x7.z;
        acc.w += v0*x0.w + v1*x1.w + v2*x2.w + v3*x3.w + v4*x4.w + v5*x5.w + v6*x6.w + v7*x7.w;
    }
    float4* dst = (float4*)((dst_id == 1) ? g_H1 : g_H2);
    dst[m * 64 + d4] = acc;
}

// ---------------- fused: ZT tile GEMM + partial M (grid 32 x 3) ----------------
__global__ void k_ZM(const float* __restrict__ H0, const float* __restrict__ U) {
    __shared__ float Hs[128 * 33];   // padded: bank = (row + col) & 31
    __shared__ float Us[32][32];
    int kz = blockIdx.y;
    const float* src = (kz == 0) ? H0 : (kz == 1) ? g_H1 : g_H2;
    const float* Uk = U + kz * Dd * Rr;
    int n0 = blockIdx.x * 128;
    int tx = threadIdx.x & 15;   // col pair r = tx*2, tx*2+1
    int ty = threadIdx.x >> 4;   // rows ty*8 .. ty*8+7
    float acc[8][2];
    #pragma unroll
    for (int q = 0; q < 8; q++) { acc[q][0] = 0.f; acc[q][1] = 0.f; }
    for (int d0 = 0; d0 < Dd; d0 += 32) {
        const float4* s4 = (const float4*)(src + (size_t)n0 * Dd + d0);
        int rr = threadIdx.x >> 3, cc = threadIdx.x & 7;
        #pragma unroll
        for (int q = 0; q < 4; q++) {
            float4 v = s4[(rr + q * 32) * 64 + cc];
            float* hp = &Hs[(rr + q * 32) * 33 + cc * 4];
            hp[0] = v.x; hp[1] = v.y; hp[2] = v.z; hp[3] = v.w;
        }
        int kk = threadIdx.x >> 3, c4 = threadIdx.x & 7;
        *(float4*)&Us[kk][c4 * 4] = *(const float4*)&Uk[(d0 + kk) * Rr + c4 * 4];
        __syncthreads();
        #pragma unroll
        for (int k2 = 0; k2 < 32; k2++) {
            float b0 = Us[k2][tx * 2], b1 = Us[k2][tx * 2 + 1];
            #pragma unroll
            for (int q = 0; q < 8; q++) {
                float a = Hs[(ty * 8 + q) * 33 + k2];
                acc[q][0] += a * b0; acc[q][1] += a * b1;
            }
        }
        __syncthreads();
    }
    // write ZT and stash tile in smem (reuse Hs as [128][33] z-tile)
    #pragma unroll
    for (int q = 0; q < 8; q++) {
        int n = ty * 8 + q;
        *(float2*)&g_ZT[kz * Nn * Rr + (n0 + n) * Rr + tx * 2] = make_float2(acc[q][0], acc[q][1]);
        Hs[n * 33 + tx * 2] = acc[q][0];
        Hs[n * 33 + tx * 2 + 1] = acc[q][1];
    }
    __syncthreads();
    // partial M over this 128-node chunk: thread owns 2x2 of the 32x32 output
    int i0 = (threadIdx.x >> 4) * 2, j0 = (threadIdx.x & 15) * 2;
    float a00 = 0.f, a01 = 0.f, a10 = 0.f, a11 = 0.f;
    #pragma unroll 4
    for (int n = 0; n < 128; n++) {
        float zi0 = Hs[n * 33 + i0], zi1 = Hs[n * 33 + i0 + 1];
        float zj0 = Hs[n * 33 + j0], zj1 = Hs[n * 33 + j0 + 1];
        a00 += zi0 * zj0; a01 += zi0 * zj1;
        a10 += zi1 * zj0; a11 += zi1 * zj1;
    }
    float* p = g_part + (kz * 32 + blockIdx.x) * Rr * Rr;
    p[i0 * 32 + j0] = a00; p[i0 * 32 + j0 + 1] = a01;
    p[(i0 + 1) * 32 + j0] = a10; p[(i0 + 1) * 32 + j0 + 1] = a11;
}

// ---------------- reduce + Cholesky + inverse (3 blocks of 1024) ----------------
__global__ void k_cholinv() {
    __shared__ float Msh[Rr * 33];
    __shared__ float ysh[Rr * 33];
    int kz = blockIdx.x;
    int tid = threadIdx.x;
    int i = tid >> 5, j = tid & 31;
    float s = 0.0f;
    #pragma unroll
    for (int b = 0; b < 32; b++) s += g_part[(kz * 32 + b) * Rr * Rr + tid];
    Msh[i * 33 + j] = COEFF * s + (i == j ? 1.0f : 0.0f);
    __syncthreads();
    for (int k2 = 0; k2 < Rr; k2++) {
        if (tid == 0) Msh[k2 * 33 + k2] = sqrtf(Msh[k2 * 33 + k2]);
        __syncthreads();
        if (j == k2 && i > k2) Msh[i * 33 + k2] /= Msh[k2 * 33 + k2];
        __syncthreads();
        if (i > k2 && j > k2 && j <= i) Msh[i * 33 + j] -= Msh[i * 33 + k2] * Msh[j * 33 + k2];
        __syncthreads();
    }
    int c = i, lane = j;
    for (int r = 0; r < Rr; r++) {
        float contrib = (lane < r) ? Msh[r * 33 + lane] * ysh[c * 33 + lane] : 0.0f;
        contrib = warp_sum(contrib);
        if (lane == 0) ysh[c * 33 + r] = (((r == c) ? 1.0f : 0.0f) - contrib) / Msh[r * 33 + r];
        __syncwarp();
    }
    for (int r = Rr - 1; r >= 0; r--) {
        float contrib = (lane > r) ? Msh[lane * 33 + r] * ysh[c * 33 + lane] : 0.0f;
        contrib = warp_sum(contrib);
        if (lane == 0) ysh[c * 33 + r] = (ysh[c * 33 + r] - contrib) / Msh[r * 33 + r];
        __syncwarp();
    }
    __syncthreads();
    g_Minv[kz * Rr * Rr + i * 32 + j] = ysh[j * 33 + i];   // Minv[i][c=j]
}

// ---------------- attention: applies Minv in-kernel (no MZ pass), warp per row ----------------
__global__ void k_attn() {
    __shared__ float Mi[Rr * 33];
    __shared__ float ssh[8][MAXNZ];
    int kz = blockIdx.y;
    int tid = threadIdx.x;
    for (int q = tid; q < Rr * Rr; q += 256)
        Mi[(q >> 5) * 33 + (q & 31)] = g_Minv[kz * Rr * Rr + q];
    __syncthreads();
    int w = tid >> 5, lane = tid & 31;
    int m = blockIdx.x * 8 + w;
    int nz = g_nnz[m];
    const int* cp = &g_cols[m * MAXNZ];
    const float* ZTk = g_ZT + kz * Nn * Rr;
    float z = ZTk[m * Rr + lane];
    // q'[s] = sum_r z[r] * Minv[r][s]
    float qp = 0.0f;
    #pragma unroll
    for (int r = 0; r < Rr; r++)
        qp += Mi[r * 33 + lane] * __shfl_sync(0xFFFFFFFFu, z, r);
    // scores over neighbors
    for (int i0 = 0; i0 < nz; i0 += 4) {
        int c0 = cp[i0];
        int c1 = (i0 + 1 < nz) ? cp[i0 + 1] : c0;
        int c2 = (i0 + 2 < nz) ? cp[i0 + 2] : c0;
        int c3 = (i0 + 3 < nz) ? cp[i0 + 3] : c0;
        float p0 = warp_sum(qp * ZTk[c0 * Rr + lane]);
        float p1 = warp_sum(qp * ZTk[c1 * Rr + lane]);
        float p2 = warp_sum(qp * ZTk[c2 * Rr + lane]);
        float p3 = warp_sum(qp * ZTk[c3 * Rr + lane]);
        if (lane == 0) {
            ssh[w][i0] = p0;
            if (i0 + 1 < nz) ssh[w][i0 + 1] = p1;
            if (i0 + 2 < nz) ssh[w][i0 + 2] = p2;
            if (i0 + 3 < nz) ssh[w][i0 + 3] = p3;
        }
    }
    __syncwarp();
    float mx = -1e30f;
    for (int i = lane; i < nz; i += 32) mx = fmaxf(mx, ssh[w][i]);
    mx = warp_max(mx);
    float sm = 0.0f;
    for (int i = lane; i < nz; i += 32) {
        float e = expf(ssh[w][i] - mx);
        ssh[w][i] = e; sm += e;
    }
    sm = warp_sum(sm);
    float inv = 1.0f / sm;
    __syncwarp();
    // t = sum_j alpha_j * z_j
    float t = 0.0f;
    int i = 0;
    for (; i + 4 <= nz; i += 4) {
        float m0 = ZTk[cp[i]     * Rr + lane];
        float m1 = ZTk[cp[i + 1] * Rr + lane];
        float m2 = ZTk[cp[i + 2] * Rr + lane];
        float m3 = ZTk[cp[i + 3] * Rr + lane];
        t += ssh[w][i] * m0 + ssh[w][i + 1] * m1 + ssh[w][i + 2] * m2 + ssh[w][i + 3] * m3;
    }
    for (; i < nz; i++) t += ssh[w][i] * ZTk[cp[i] * Rr + lane];
    t *= inv;
    // out[r] = sum_s Minv[r][s] * t[s]
    float o = 0.0f;
    #pragma unroll
    for (int s2 = 0; s2 < Rr; s2++)
        o += Mi[lane * 33 + s2] * __shfl_sync(0xFFFFFFFFu, t, s2);
    g_Gcat[m * (Kk * Rr) + kz * Rr + lane] = o * (ETA * g_w[kz]);
}

// ---------------- agg = Gcat @ Ucat: tiled 64x64, 4x4 per thread ----------------
__global__ void k_gemm(const float* __restrict__ U) {
    __shared__ float Gs[64][33];
    __shared__ float Us[32][65];
    int n0 = blockIdx.x * 64, d0 = blockIdx.y * 64;
    int tx = threadIdx.x & 15, ty = threadIdx.x >> 4;
    float acc[4][4];
    #pragma unroll
    for (int a = 0; a < 4; a++)
        #pragma unroll
        for (int b = 0; b < 4; b++) acc[a][b] = 0.f;
    for (int k = 0; k < Kk; k++) {
        __syncthreads();
        #pragma unroll
        for (int q = 0; q < 8; q++) {
            int idx = threadIdx.x + 256 * q;
            int gi = idx >> 5, gr = idx & 31;
            Gs[gi][gr] = g_Gcat[(n0 + gi) * (Kk * Rr) + k * Rr + gr];
            Us[gr][gi] = U[k * Dd * Rr + (d0 + gi) * Rr + gr];
        }
        __syncthreads();
        #pragma unroll
        for (int r = 0; r < Rr; r++) {
            float a[4], b[4];
            #pragma unroll
            for (int q = 0; q < 4; q++) a[q] = Gs[ty * 4 + q][r];
            #pragma unroll
            for (int p = 0; p < 4; p++) b[p] = Us[r][tx * 4 + p];
            #pragma unroll
            for (int q = 0; q < 4; q++)
                #pragma unroll
                for (int p = 0; p < 4; p++) acc[q][p] += a[q] * b[p];
        }
    }
    #pragma unroll
    for (int q = 0; q < 4; q++) {
        float4 v = make_float4(acc[q][0], acc[q][1], acc[q][2], acc[q][3]);
        *(float4*)&g_agg[(size_t)(n0 + ty * 4 + q) * Dd + d0 + tx * 4] = v;
    }
}

// ---------------- finalize: inline H3 gather + threshold + residual + LN; 4 rows/block ----------------
__global__ void k_finalize(const float* __restrict__ H0, const float* __restrict__ thr,
                           const float* __restrict__ gam, const float* __restrict__ bet,
                           float* __restrict__ out) {
    int rl = threadIdx.x >> 6, t64 = threadIdx.x & 63;
    int m = blockIdx.x * 4 + rl;
    __shared__ int   csh[4][MAXNZ];
    __shared__ float vsh[4][MAXNZ];
    __shared__ float wred[8][2];
    int nzp = g_nnzp[m];
    for (int i = t64; i < nzp; i += 64) {
        csh[rl][i] = g_cols[m * MAXNZ + i];
        vsh[rl][i] = g_vals[m * MAXNZ + i];
    }
    __syncthreads();
    const float4* H0_4 = (const float4*)H0;
    const float4* H1_4 = (const float4*)g_H1;
    const float4* H2_4 = (const float4*)g_H2;
    const float4* ag4  = (const float4*)g_agg;
    int idx4 = m * 64 + t64;
    float4 x  = H0_4[idx4];
    float4 h1 = H1_4[idx4];
    float4 h2 = H2_4[idx4];
    float4 ag = ag4[idx4];
    // h3 = (A @ H2)[m]
    float4 h3 = make_float4(0.f, 0.f, 0.f, 0.f);
    for (int i = 0; i < nzp; i += 4) {
        float4 x0 = H2_4[csh[rl][i]     * 64 + t64];
        float4 x1 = H2_4[csh[rl][i + 1] * 64 + t64];
        float4 x2 = H2_4[csh[rl][i + 2] * 64 + t64];
        float4 x3 = H2_4[csh[rl][i + 3] * 64 + t64];
        float v0 = vsh[rl][i], v1 = vsh[rl][i + 1], v2 = vsh[rl][i + 2], v3 = vsh[rl][i + 3];
        h3.x += v0*x0.x + v1*x1.x + v2*x2.x + v3*x3.x;
        h3.y += v0*x0.y + v1*x1.y + v2*x2.y + v3*x3.y;
        h3.z += v0*x0.z + v1*x1.z + v2*x2.z + v3*x3.z;
        h3.w += v0*x0.w + v1*x1.w + v2*x2.w + v3*x3.w;
    }
    float l0 = g_lap[0], l1 = g_lap[1], l2 = g_lap[2];
    float4 t4 = ((const float4*)thr)[t64];
    float y[4];
    {
        float xs[4] = {x.x, x.y, x.z, x.w};
        float a1[4] = {h1.x, h1.y, h1.z, h1.w};
        float a2[4] = {h2.x, h2.y, h2.z, h2.w};
        float a3[4] = {h3.x, h3.y, h3.z, h3.w};
        float ags[4] = {ag.x, ag.y, ag.z, ag.w};
        float ts[4] = {t4.x, t4.y, t4.z, t4.w};
        #pragma unroll
        for (int q = 0; q < 4; q++) {
            float lap = l0 * (xs[q] - a1[q]) + l1 * (a1[q] - a2[q]) + l2 * (a2[q] - a3[q]);
            float h = xs[q] + ags[q] - ETA * lap;
            float a = fabsf(h) - ts[q];
            float yv = (a > 0.0f) ? copysignf(a, h) : 0.0f;
            y[q] = yv + xs[q];
        }
    }
    float s1 = y[0] + y[1] + y[2] + y[3];
    float s2 = y[0]*y[0] + y[1]*y[1] + y[2]*y[2] + y[3]*y[3];
    s1 = warp_sum(s1); s2 = warp_sum(s2);
    int w = threadIdx.x >> 5, lane = threadIdx.x & 31;
    if (lane == 0) { wred[w][0] = s1; wred[w][1] = s2; }
    __syncthreads();
    float mu  = (wred[rl*2][0] + wred[rl*2+1][0]) * (1.0f / Dd);
    float ex2 = (wred[rl*2][1] + wred[rl*2+1][1]) * (1.0f / Dd);
    float inv_sd = rsqrtf(ex2 - mu * mu + LN_EPS);
    float4 g4 = ((const float4*)gam)[t64];
    float4 b4 = ((const float4*)bet)[t64];
    float4 o4;
    o4.x = (y[0] - mu) * inv_sd * g4.x + b4.x;
    o4.y = (y[1] - mu) * inv_sd * g4.y + b4.y;
    o4.z = (y[2] - mu) * inv_sd * g4.z + b4.z;
    o4.w = (y[3] - mu) * inv_sd * g4.w + b4.w;
    ((float4*)out)[idx4] = o4;
}

// ---------------- lap_smooth = sum(H_out * (H_out - A@H_out)); 4 rows/block ----------------
__global__ void k_lapsm(const float* __restrict__ out, float* __restrict__ dst) {
    int rl = threadIdx.x >> 6, t64 = threadIdx.x & 63;
    int m = blockIdx.x * 4 + rl;
    __shared__ int   csh[4][MAXNZ];
    __shared__ float vsh[4][MAXNZ];
    __shared__ float wred[8];
    int nzp = g_nnzp[m];
    for (int i = t64; i < nzp; i += 64) {
        csh[rl][i] = g_cols[m * MAXNZ + i];
        vsh[rl][i] = g_vals[m * MAXNZ + i];
    }
    __syncthreads();
    const float4* o4 = (const float4*)out;
    float4 o = o4[m * 64 + t64];
    float4 ah = make_float4(0.f, 0.f, 0.f, 0.f);
    for (int i = 0; i < nzp; i += 4) {
        float4 x0 = o4[csh[rl][i]     * 64 + t64];
        float4 x1 = o4[csh[rl][i + 1] * 64 + t64];
        float4 x2 = o4[csh[rl][i + 2] * 64 + t64];
        float4 x3 = o4[csh[rl][i + 3] * 64 + t64];
        float v0 = vsh[rl][i], v1 = vsh[rl][i + 1], v2 = vsh[rl][i + 2], v3 = vsh[rl][i + 3];
        ah.x += v0*x0.x + v1*x1.x + v2*x2.x + v3*x3.x;
        ah.y += v0*x0.y + v1*x1.y + v2*x2.y + v3*x3.y;
        ah.z += v0*x0.z + v1*x1.z + v2*x2.z + v3*x3.z;
        ah.w += v0*x0.w + v1*x1.w + v2*x2.w + v3*x3.w;
    }
    float part = o.x * (o.x - ah.x) + o.y * (o.y - ah.y) + o.z * (o.z - ah.z) + o.w * (o.w - ah.w);
    int w = threadIdx.x >> 5, lane = threadIdx.x & 31;
    float s = warp_sum(part);
    if (lane == 0) wred[w] = s;
    __syncthreads();
    if (threadIdx.x == 0) {
        float t = 0.0f;
        #pragma unroll
        for (int q = 0; q < 8; q++) t += wred[q];
        atomicAdd(dst, t);
    }
}

// ---------------- orthogonality loss ----------------
__global__ void k_orth(const float* __restrict__ U, float* __restrict__ dst) {
    const int pk[6] = {0,0,0,1,1,2}, pl[6] = {0,1,2,1,2,2};
    int k = pk[blockIdx.x], l = pl[blockIdx.x];
    int a = threadIdx.x >> 5, b = threadIdx.x & 31;
    const float* Ua = U + k * Dd * Rr;
    const float* Ub = U + l * Dd * Rr;
    float g = 0.0f;
    #pragma unroll 8
    for (int d = 0; d < Dd; d++) g += Ua[d * Rr + a] * Ub[d * Rr + b];
    if (k == l && a == b) g -= 1.0f;
    g *= g;
    __shared__ float wred[32];
    int w = threadIdx.x >> 5, lane = threadIdx.x & 31;
    float s = warp_sum(g);
    if (lane == 0) wred[w] = s;
    __syncthreads();
    if (threadIdx.x < 32) {
        float t = wred[threadIdx.x];
        t = warp_sum(t);
        if (threadIdx.x == 0) atomicAdd(dst, t);
    }
}

// ---------------- launch ----------------
extern "C" void kernel_launch(void* const* d_in, const int* in_sizes, int n_in,
                              void* d_out, int out_size) {
    const float* H   = (const float*)d_in[0];
    const float* A   = (const float*)d_in[1];
    const float* U   = (const float*)d_in[4];
    const float* lam = (const float*)d_in[5];
    const float* hw  = (const float*)d_in[6];
    const float* thr = (const float*)d_in[7];
    const float* gam = (const float*)d_in[8];
    const float* bet = (const float*)d_in[9];
    float* out  = (float*)d_out;
    float* tail = out + (size_t)Nn * Dd;   // [orth, lap_smooth, w0, w1, w2]

    k_setup<<<1, 32>>>(lam, hw, tail);
    k_csr<<<Nn / 8, 256>>>(A);
    k_orth<<<6, 1024>>>(U, tail + 0);

    k_spmm<<<Nn / 4, 256>>>(H, 0, 1);   // H1 = A @ H
    k_spmm<<<Nn / 4, 256>>>(H, 1, 2);   // H2 = A @ H1

    k_ZM<<<dim3(32, Kk), 256>>>(H, U);  // ZT + partial M, fused
    k_cholinv<<<Kk, 1024>>>();
    k_attn<<<dim3(Nn / 8, Kk), 256>>>();

    k_gemm<<<dim3(Nn / 64, Dd / 64), 256>>>(U);
    k_finalize<<<Nn / 4, 256>>>(H, thr, gam, bet, out);  // includes H3 gather
    k_lapsm<<<Nn / 4, 256>>>(out, tail + 1);
}